// round 13
// baseline (speedup 1.0000x reference)
#include <cuda_runtime.h>

// SparseBiasDiagUnfolder — output-centric + one wave + MLP=4.
//   adj: (B=2, N=2048, N=2048, F=16) fp32; starts 0,4,...,2040 (511);
//   out (B, 511, 56*16) = 228,928 float4s.
//
// 146 blocks x 448 threads (one wave), each thread handles 4 output float4s
// grid-strided by 65,408: stores are perfectly lane-contiguous per item and
// all 32 lanes active (no diagonal predication). 4 independent loads batched
// up front (clamped index so loads stay unconditional); only the 4th store
// is bound-checked (items 0..2 always valid: 3*65408 + tid < 228928 holds
// for tid < 32704... actually checked per item for safety on item 3).
//
// Index math per item (all 32-bit, div-free except one magic-multiply /7):
//   warp chunk: w = idx>>5, lane = idx&31
//   bs = w/7 (w*149797>>20, exact for w<349525), u = w-7bs
//   pos = 8u + lane>>2, v = lane&3, local = pos+1+u, ii = local>>3, jj = local&7
//   b = bs>=511, s = bs-511b
//   src = b*N*N*4 + s*(N+1)*16 + (ii*N+jj)*4 + v

namespace {
constexpr int N         = 2048;
constexpr int NSTARTS   = 511;
constexpr int TOTAL_VEC = 2 * NSTARTS * 56 * 4;   // 228,928
constexpr int THREADS   = 448;
constexpr int BLOCKS    = 146;                    // one wave
constexpr int TSTRIDE   = BLOCKS * THREADS;       // 65,408
constexpr int ITEMS     = 4;                      // 65,408*4 = 261,632 >= TOTAL
}

__device__ __forceinline__ unsigned src_index(unsigned idx)
{
    const unsigned w    = idx >> 5;
    const unsigned lane = idx & 31u;

    const unsigned bs = (w * 149797u) >> 20;      // w / 7 (exact)
    const unsigned u  = w - bs * 7u;

    const unsigned pos   = u * 8u + (lane >> 2);
    const unsigned v     = lane & 3u;
    const unsigned local = pos + 1u + u;          // skip diagonal
    const unsigned ii    = local >> 3;
    const unsigned jj    = local & 7u;

    const unsigned b = (bs >= NSTARTS);
    const unsigned s = bs - b * NSTARTS;

    return b * (N * N * 4u)
         + s * ((N + 1) * 16u)
         + (ii * N + jj) * 4u
         + v;
}

__global__ void __launch_bounds__(THREADS)
sparse_diag_unfold_kernel(const float4* __restrict__ adj, float4* __restrict__ out)
{
    const unsigned tid = blockIdx.x * THREADS + threadIdx.x;

    // 4 independent loads batched up front (clamped -> unconditional).
    float4 vals[ITEMS];
    #pragma unroll
    for (int k = 0; k < ITEMS; k++) {
        unsigned idx = tid + (unsigned)k * TSTRIDE;
        unsigned c   = idx < TOTAL_VEC ? idx : (TOTAL_VEC - 1u);
        vals[k] = adj[src_index(c)];
    }

    // Perfectly coalesced stores; only out-of-range items predicated.
    #pragma unroll
    for (int k = 0; k < ITEMS; k++) {
        unsigned idx = tid + (unsigned)k * TSTRIDE;
        if (idx < TOTAL_VEC) out[idx] = vals[k];
    }
}

extern "C" void kernel_launch(void* const* d_in, const int* in_sizes, int n_in,
                              void* d_out, int out_size)
{
    const float4* adj = (const float4*)d_in[0];
    float4* out = (float4*)d_out;
    sparse_diag_unfold_kernel<<<BLOCKS, THREADS>>>(adj, out);
}